// round 11
// baseline (speedup 1.0000x reference)
#include <cuda_runtime.h>
#include <cstdint>

#define N_NODES 100000
#define N_EDGES 1600000
#define IN_F    128
#define OUT_F   32

typedef unsigned long long u64;

// Scratch (__device__ globals; no allocation anywhere in this file).
__device__ int   g_deg[N_NODES];
__device__ u64   g_W2 [(IN_F / 2) * OUT_F];   // packed W pairs: [k2][f]
__device__ float g_hs [N_NODES * OUT_F];      // h * dis[node] (self-term & message)
__device__ __align__(16) int g_ptr [N_NODES + 4];   // CSR row offsets (exclusive scan of indeg)
__device__ __align__(16) int g_fill[N_NODES + 4];   // fill cursors (mutated by k_csr)
__device__ int   g_part[128];                 // block partials for scan
__device__ int   g_csrc[N_EDGES];             // CSR: src ids bucketed by dst

// ---------------------------------------------------------------------------
// K1: deg=1 (self loop) + one-shot W pair packing.
__global__ void k_init(const float* __restrict__ W) {
    int i = blockIdx.x * blockDim.x + threadIdx.x;
    if (i < N_NODES) g_deg[i] = 1;
    if (i < (IN_F / 2) * OUT_F) {
        int k2 = i >> 5;
        int f  = i & 31;
        float w0 = W[f * IN_F + 2 * k2];
        float w1 = W[f * IN_F + 2 * k2 + 1];
        g_W2[i] = ((u64)__float_as_uint(w1) << 32) | (u64)__float_as_uint(w0);
    }
}

__global__ void k_deg_count(const int* __restrict__ ei) {
    int e = blockIdx.x * blockDim.x + threadIdx.x;
    if (e < N_EDGES) atomicAdd(&g_deg[ei[N_EDGES + e]], 1);
}

// ---------------------------------------------------------------------------
// Scan of indeg (= deg-1) over N_NODES. 1024 elems/block, 256 threads (4/thread).
#define SCAN_NB ((N_NODES + 1023) / 1024)     // 98

__device__ __forceinline__ int4 load_indeg4(int i0) {
    int4 v;
    v.x = (i0 + 0 < N_NODES) ? g_deg[i0 + 0] - 1 : 0;
    v.y = (i0 + 1 < N_NODES) ? g_deg[i0 + 1] - 1 : 0;
    v.z = (i0 + 2 < N_NODES) ? g_deg[i0 + 2] - 1 : 0;
    v.w = (i0 + 3 < N_NODES) ? g_deg[i0 + 3] - 1 : 0;
    return v;
}

__global__ __launch_bounds__(256) void k_scan1() {       // block partial sums
    __shared__ int ws[8];
    int t = threadIdx.x, lane = t & 31, wid = t >> 5;
    int4 v = load_indeg4(blockIdx.x * 1024 + t * 4);
    int s = v.x + v.y + v.z + v.w;
    #pragma unroll
    for (int o = 16; o > 0; o >>= 1) s += __shfl_down_sync(0xffffffffu, s, o);
    if (lane == 0) ws[wid] = s;
    __syncthreads();
    if (t == 0) {
        int p = 0;
        #pragma unroll
        for (int w = 0; w < 8; w++) p += ws[w];
        g_part[blockIdx.x] = p;
    }
}

__global__ void k_scan2() {                              // exclusive scan of partials
    __shared__ int sp[SCAN_NB];
    int t = threadIdx.x;
    if (t < SCAN_NB) sp[t] = g_part[t];
    __syncthreads();
    if (t == 0) {
        int run = 0;
        for (int i = 0; i < SCAN_NB; i++) { int v = sp[i]; sp[i] = run; run += v; }
    }
    __syncthreads();
    if (t < SCAN_NB) g_part[t] = sp[t];
}

__global__ __launch_bounds__(256) void k_scan3() {       // full exclusive scan -> ptr, fill
    __shared__ int ws[8];
    __shared__ int wexcl_s[8];
    int t = threadIdx.x, lane = t & 31, wid = t >> 5;
    int i0 = blockIdx.x * 1024 + t * 4;
    int4 v = load_indeg4(i0);
    int s01  = v.x + v.y;
    int s012 = s01 + v.z;
    int tsum = s012 + v.w;

    int inc = tsum;                                      // warp inclusive scan
    #pragma unroll
    for (int o = 1; o < 32; o <<= 1) {
        int n = __shfl_up_sync(0xffffffffu, inc, o);
        if (lane >= o) inc += n;
    }
    if (lane == 31) ws[wid] = inc;
    __syncthreads();
    if (wid == 0) {
        int wv = (lane < 8) ? ws[lane] : 0;
        int wi = wv;
        #pragma unroll
        for (int o = 1; o < 8; o <<= 1) {
            int n = __shfl_up_sync(0xffffffffu, wi, o);
            if (lane >= o) wi += n;
        }
        if (lane < 8) wexcl_s[lane] = wi - wv;
    }
    __syncthreads();

    int texcl = g_part[blockIdx.x] + wexcl_s[wid] + (inc - tsum);
    int4 p = make_int4(texcl, texcl + v.x, texcl + s01, texcl + s012);
    if (i0 + 3 < N_NODES) {
        *(int4*)&g_ptr [i0] = p;
        *(int4*)&g_fill[i0] = p;
    } else {
        int pv[4] = {p.x, p.y, p.z, p.w};
        for (int j = 0; j < 4 && i0 + j < N_NODES; j++) {
            g_ptr[i0 + j] = pv[j]; g_fill[i0 + j] = pv[j];
        }
    }
    if (blockIdx.x == 0 && t == 0) g_ptr[N_NODES] = N_EDGES;
}

// ---------------------------------------------------------------------------
// CSR build: bucket src ids by dst (order within bucket nondeterministic; sum
// order-independence covered by rel_err budget, same class as RED before).
__global__ void k_csr(const int* __restrict__ ei) {
    int e = blockIdx.x * blockDim.x + threadIdx.x;
    if (e < N_EDGES) {
        int dst = ei[N_EDGES + e];
        int pos = atomicAdd(&g_fill[dst], 1);
        g_csrc[pos] = ei[e];
    }
}

// ---------------------------------------------------------------------------
// K4: h = x @ W^T via packed f32x2 FMA, operands staged through shared.
#define NODES_PER_WARP 8
#define NODES_PER_BLK  64
#define FFMA2(acc, a, b) \
    asm("fma.rn.f32x2 %0, %1, %2, %0;" : "+l"(acc) : "l"(a), "l"(b))
#define CP_ASYNC16(saddr, gptr) \
    asm volatile("cp.async.cg.shared.global [%0], [%1], 16;" \
                 :: "r"(saddr), "l"(gptr) : "memory")

__global__ __launch_bounds__(256) void k_linear(const float* __restrict__ x) {
    __shared__ u64   sW2[IN_F / 2][OUT_F];
    __shared__ float sx[NODES_PER_BLK][IN_F];

    int tid = threadIdx.x;
    int node0 = blockIdx.x * NODES_PER_BLK;
    bool full = (node0 + NODES_PER_BLK <= N_NODES);

    const float4* xg = (const float4*)(x + (size_t)node0 * IN_F);
    float4* sx4 = (float4*)sx;
    if (full) {
        unsigned sbase;
        asm("{ .reg .u64 t; cvta.to.shared.u64 t, %1; cvt.u32.u64 %0, t; }"
            : "=r"(sbase) : "l"(sx4));
        #pragma unroll
        for (int i = 0; i < 8; i++) {
            int idx = tid + i * 256;
            CP_ASYNC16(sbase + idx * 16, xg + idx);
        }
        asm volatile("cp.async.commit_group;" ::: "memory");
    } else {
        #pragma unroll
        for (int i = 0; i < 8; i++) {
            int idx = tid + i * 256;
            sx4[idx] = (node0 + (idx >> 5) < N_NODES) ? xg[idx]
                                                      : make_float4(0.f, 0.f, 0.f, 0.f);
        }
    }

    {
        u64* sW = &sW2[0][0];
        #pragma unroll
        for (int i = 0; i < 8; i++)
            sW[tid + i * 256] = g_W2[tid + i * 256];
    }

    if (full) asm volatile("cp.async.wait_group 0;" ::: "memory");
    __syncthreads();

    int warp = tid >> 5;
    int f    = tid & 31;
    int nb   = warp * NODES_PER_WARP;

    u64 acc2[NODES_PER_WARP];
    #pragma unroll
    for (int n = 0; n < NODES_PER_WARP; n++) acc2[n] = 0ull;

    #pragma unroll 8
    for (int k4 = 0; k4 < IN_F / 4; k4++) {
        u64 wa = sW2[2 * k4 + 0][f];
        u64 wb = sW2[2 * k4 + 1][f];
        #pragma unroll
        for (int n = 0; n < NODES_PER_WARP; n++) {
            ulonglong2 xv = *(const ulonglong2*)&sx[nb + n][k4 * 4];
            FFMA2(acc2[n], xv.x, wa);
            FFMA2(acc2[n], xv.y, wb);
        }
    }

    #pragma unroll
    for (int n = 0; n < NODES_PER_WARP; n++) {
        int node = node0 + nb + n;
        if (node < N_NODES) {
            float lo = __uint_as_float((unsigned)(acc2[n] & 0xFFFFFFFFull));
            float hi = __uint_as_float((unsigned)(acc2[n] >> 32));
            float d  = rsqrtf((float)g_deg[node]);
            g_hs[node * OUT_F + f] = (lo + hi) * d;   // self-term == message value
        }
    }
}

// ---------------------------------------------------------------------------
// K5: aggregate + finalize. Warp per node, lane = feature. Pure gather, plain
// coalesced 128B stores to d_out. MLP=2 on the row gathers.
__global__ __launch_bounds__(256) void k_aggregate(const float* __restrict__ b,
                                                   float* __restrict__ out) {
    int gtid = blockIdx.x * blockDim.x + threadIdx.x;
    int node = gtid >> 5;
    int lane = gtid & 31;

    float acc = g_hs[node * OUT_F + lane];            // self-loop term
    int j   = g_ptr[node];
    int end = g_ptr[node + 1];

    for (; j + 2 <= end; j += 2) {
        int s0 = g_csrc[j];
        int s1 = g_csrc[j + 1];
        float v0 = g_hs[s0 * OUT_F + lane];           // 2 independent gathers
        float v1 = g_hs[s1 * OUT_F + lane];
        acc += v0;
        acc += v1;
    }
    if (j < end) acc += g_hs[g_csrc[j] * OUT_F + lane];

    float d = rsqrtf((float)g_deg[node]);
    out[node * OUT_F + lane] = fmaf(acc, d, b[lane]);
}

// ---------------------------------------------------------------------------
extern "C" void kernel_launch(void* const* d_in, const int* in_sizes, int n_in,
                              void* d_out, int out_size) {
    const float* x  = (const float*)d_in[0];
    const int*   ei = (const int*)d_in[1];     // int32 (harness downcasts int64)
    const float* W  = (const float*)d_in[2];
    const float* b  = (const float*)d_in[3];
    float*       out = (float*)d_out;

    (void)in_sizes; (void)n_in; (void)out_size;

    k_init     <<<(N_NODES + 255) / 256, 256>>>(W);
    k_deg_count<<<(N_EDGES + 255) / 256, 256>>>(ei);
    k_scan1    <<<SCAN_NB, 256>>>();
    k_scan2    <<<1, 128>>>();
    k_scan3    <<<SCAN_NB, 256>>>();
    k_csr      <<<(N_EDGES + 255) / 256, 256>>>(ei);
    k_linear   <<<(N_NODES + NODES_PER_BLK - 1) / NODES_PER_BLK, 256>>>(x);
    k_aggregate<<<(N_NODES * 32) / 256, 256>>>(b, out);
}

// round 12
// speedup vs baseline: 1.0025x; 1.0025x over previous
#include <cuda_runtime.h>
#include <cstdint>

#define N_NODES 100000
#define N_EDGES 1600000
#define IN_F    128
#define OUT_F   32

typedef unsigned long long u64;

// Scratch (__device__ globals; no allocation anywhere in this file).
__device__ int   g_deg[N_NODES];
__device__ u64   g_W2 [(IN_F / 2) * OUT_F];   // packed W pairs: [k2][f]
__device__ float g_hs [N_NODES * OUT_F];      // h * dis[node] (self-term & message)
__device__ __align__(16) int g_ptr [N_NODES + 4];   // CSR row offsets
__device__ __align__(16) int g_fill[N_NODES + 4];   // fill cursors (mutated by k_csr)
__device__ int   g_part[128];                 // block partials for scan
__device__ int   g_csrc[N_EDGES];             // CSR: src ids bucketed by dst

// ---------------------------------------------------------------------------
// K1: deg=1 (self loop) + one-shot W pair packing.
__global__ void k_init(const float* __restrict__ W) {
    int i = blockIdx.x * blockDim.x + threadIdx.x;
    if (i < N_NODES) g_deg[i] = 1;
    if (i < (IN_F / 2) * OUT_F) {
        int k2 = i >> 5;
        int f  = i & 31;
        float w0 = W[f * IN_F + 2 * k2];
        float w1 = W[f * IN_F + 2 * k2 + 1];
        g_W2[i] = ((u64)__float_as_uint(w1) << 32) | (u64)__float_as_uint(w0);
    }
}

__global__ void k_deg_count(const int* __restrict__ ei) {
    int e = blockIdx.x * blockDim.x + threadIdx.x;
    if (e < N_EDGES) atomicAdd(&g_deg[ei[N_EDGES + e]], 1);
}

// ---------------------------------------------------------------------------
// Scan of indeg (= deg-1) over N_NODES. 1024 elems/block, 256 threads.
#define SCAN_NB ((N_NODES + 1023) / 1024)     // 98

__device__ __forceinline__ int4 load_indeg4(int i0) {
    int4 v;
    v.x = (i0 + 0 < N_NODES) ? g_deg[i0 + 0] - 1 : 0;
    v.y = (i0 + 1 < N_NODES) ? g_deg[i0 + 1] - 1 : 0;
    v.z = (i0 + 2 < N_NODES) ? g_deg[i0 + 2] - 1 : 0;
    v.w = (i0 + 3 < N_NODES) ? g_deg[i0 + 3] - 1 : 0;
    return v;
}

__global__ __launch_bounds__(256) void k_scan1() {       // block partial sums
    __shared__ int ws[8];
    int t = threadIdx.x, lane = t & 31, wid = t >> 5;
    int4 v = load_indeg4(blockIdx.x * 1024 + t * 4);
    int s = v.x + v.y + v.z + v.w;
    #pragma unroll
    for (int o = 16; o > 0; o >>= 1) s += __shfl_down_sync(0xffffffffu, s, o);
    if (lane == 0) ws[wid] = s;
    __syncthreads();
    if (t == 0) {
        int p = 0;
        #pragma unroll
        for (int w = 0; w < 8; w++) p += ws[w];
        g_part[blockIdx.x] = p;
    }
}

// Parallel exclusive scan of the 98 partials (warp-shuffle, 128 threads).
__global__ void k_scan2() {
    __shared__ int ws[4];
    int t = threadIdx.x, lane = t & 31, wid = t >> 5;
    int v = (t < SCAN_NB) ? g_part[t] : 0;
    int inc = v;
    #pragma unroll
    for (int o = 1; o < 32; o <<= 1) {
        int n = __shfl_up_sync(0xffffffffu, inc, o);
        if (lane >= o) inc += n;
    }
    if (lane == 31) ws[wid] = inc;
    __syncthreads();
    int wexcl = 0;
    #pragma unroll
    for (int w = 0; w < 4; w++) wexcl += (w < wid) ? ws[w] : 0;
    if (t < SCAN_NB) g_part[t] = wexcl + inc - v;        // exclusive
}

__global__ __launch_bounds__(256) void k_scan3() {       // full exclusive scan -> ptr, fill
    __shared__ int ws[8];
    __shared__ int wexcl_s[8];
    int t = threadIdx.x, lane = t & 31, wid = t >> 5;
    int i0 = blockIdx.x * 1024 + t * 4;
    int4 v = load_indeg4(i0);
    int s01  = v.x + v.y;
    int s012 = s01 + v.z;
    int tsum = s012 + v.w;

    int inc = tsum;
    #pragma unroll
    for (int o = 1; o < 32; o <<= 1) {
        int n = __shfl_up_sync(0xffffffffu, inc, o);
        if (lane >= o) inc += n;
    }
    if (lane == 31) ws[wid] = inc;
    __syncthreads();
    if (wid == 0) {
        int wv = (lane < 8) ? ws[lane] : 0;
        int wi = wv;
        #pragma unroll
        for (int o = 1; o < 8; o <<= 1) {
            int n = __shfl_up_sync(0xffffffffu, wi, o);
            if (lane >= o) wi += n;
        }
        if (lane < 8) wexcl_s[lane] = wi - wv;
    }
    __syncthreads();

    int texcl = g_part[blockIdx.x] + wexcl_s[wid] + (inc - tsum);
    int4 p = make_int4(texcl, texcl + v.x, texcl + s01, texcl + s012);
    if (i0 + 3 < N_NODES) {
        *(int4*)&g_ptr [i0] = p;
        *(int4*)&g_fill[i0] = p;
    } else {
        int pv[4] = {p.x, p.y, p.z, p.w};
        for (int j = 0; j < 4 && i0 + j < N_NODES; j++) {
            g_ptr[i0 + j] = pv[j]; g_fill[i0 + j] = pv[j];
        }
    }
    if (blockIdx.x == 0 && t == 0) g_ptr[N_NODES] = N_EDGES;
}

// ---------------------------------------------------------------------------
// CSR build: bucket src ids by dst.
__global__ void k_csr(const int* __restrict__ ei) {
    int e = blockIdx.x * blockDim.x + threadIdx.x;
    if (e < N_EDGES) {
        int dst = ei[N_EDGES + e];
        int pos = atomicAdd(&g_fill[dst], 1);
        g_csrc[pos] = ei[e];
    }
}

// ---------------------------------------------------------------------------
// K4: h = x @ W^T via packed f32x2 FMA, operands staged through shared.
#define NODES_PER_WARP 8
#define NODES_PER_BLK  64
#define FFMA2(acc, a, b) \
    asm("fma.rn.f32x2 %0, %1, %2, %0;" : "+l"(acc) : "l"(a), "l"(b))
#define CP_ASYNC16(saddr, gptr) \
    asm volatile("cp.async.cg.shared.global [%0], [%1], 16;" \
                 :: "r"(saddr), "l"(gptr) : "memory")

__global__ __launch_bounds__(256) void k_linear(const float* __restrict__ x) {
    __shared__ u64   sW2[IN_F / 2][OUT_F];
    __shared__ float sx[NODES_PER_BLK][IN_F];

    int tid = threadIdx.x;
    int node0 = blockIdx.x * NODES_PER_BLK;
    bool full = (node0 + NODES_PER_BLK <= N_NODES);

    const float4* xg = (const float4*)(x + (size_t)node0 * IN_F);
    float4* sx4 = (float4*)sx;
    if (full) {
        unsigned sbase;
        asm("{ .reg .u64 t; cvta.to.shared.u64 t, %1; cvt.u32.u64 %0, t; }"
            : "=r"(sbase) : "l"(sx4));
        #pragma unroll
        for (int i = 0; i < 8; i++) {
            int idx = tid + i * 256;
            CP_ASYNC16(sbase + idx * 16, xg + idx);
        }
        asm volatile("cp.async.commit_group;" ::: "memory");
    } else {
        #pragma unroll
        for (int i = 0; i < 8; i++) {
            int idx = tid + i * 256;
            sx4[idx] = (node0 + (idx >> 5) < N_NODES) ? xg[idx]
                                                      : make_float4(0.f, 0.f, 0.f, 0.f);
        }
    }

    {
        u64* sW = &sW2[0][0];
        #pragma unroll
        for (int i = 0; i < 8; i++)
            sW[tid + i * 256] = g_W2[tid + i * 256];
    }

    if (full) asm volatile("cp.async.wait_group 0;" ::: "memory");
    __syncthreads();

    int warp = tid >> 5;
    int f    = tid & 31;
    int nb   = warp * NODES_PER_WARP;

    u64 acc2[NODES_PER_WARP];
    #pragma unroll
    for (int n = 0; n < NODES_PER_WARP; n++) acc2[n] = 0ull;

    #pragma unroll 8
    for (int k4 = 0; k4 < IN_F / 4; k4++) {
        u64 wa = sW2[2 * k4 + 0][f];
        u64 wb = sW2[2 * k4 + 1][f];
        #pragma unroll
        for (int n = 0; n < NODES_PER_WARP; n++) {
            ulonglong2 xv = *(const ulonglong2*)&sx[nb + n][k4 * 4];
            FFMA2(acc2[n], xv.x, wa);
            FFMA2(acc2[n], xv.y, wb);
        }
    }

    #pragma unroll
    for (int n = 0; n < NODES_PER_WARP; n++) {
        int node = node0 + nb + n;
        if (node < N_NODES) {
            float lo = __uint_as_float((unsigned)(acc2[n] & 0xFFFFFFFFull));
            float hi = __uint_as_float((unsigned)(acc2[n] >> 32));
            float d  = rsqrtf((float)g_deg[node]);
            g_hs[node * OUT_F + f] = (lo + hi) * d;   // self-term == message value
        }
    }
}

// ---------------------------------------------------------------------------
// K5: aggregate + finalize. Warp per node, lane = feature. Pure gather with
// MLP=4; plain coalesced 128B stores to d_out.
__global__ __launch_bounds__(256) void k_aggregate(const float* __restrict__ b,
                                                   float* __restrict__ out) {
    int gtid = blockIdx.x * blockDim.x + threadIdx.x;
    int node = gtid >> 5;
    int lane = gtid & 31;

    float acc = g_hs[node * OUT_F + lane];            // self-loop term
    int j   = g_ptr[node];
    int end = g_ptr[node + 1];

    for (; j + 4 <= end; j += 4) {
        int s0 = g_csrc[j];                           // warp-broadcast index loads
        int s1 = g_csrc[j + 1];
        int s2 = g_csrc[j + 2];
        int s3 = g_csrc[j + 3];
        float v0 = g_hs[s0 * OUT_F + lane];           // 4 gathers in flight
        float v1 = g_hs[s1 * OUT_F + lane];
        float v2 = g_hs[s2 * OUT_F + lane];
        float v3 = g_hs[s3 * OUT_F + lane];
        acc += v0; acc += v1; acc += v2; acc += v3;
    }
    for (; j < end; j++)
        acc += g_hs[g_csrc[j] * OUT_F + lane];

    float d = rsqrtf((float)g_deg[node]);
    out[node * OUT_F + lane] = fmaf(acc, d, b[lane]);
}

// ---------------------------------------------------------------------------
extern "C" void kernel_launch(void* const* d_in, const int* in_sizes, int n_in,
                              void* d_out, int out_size) {
    const float* x  = (const float*)d_in[0];
    const int*   ei = (const int*)d_in[1];     // int32 (harness downcasts int64)
    const float* W  = (const float*)d_in[2];
    const float* b  = (const float*)d_in[3];
    float*       out = (float*)d_out;

    (void)in_sizes; (void)n_in; (void)out_size;

    k_init     <<<(N_NODES + 255) / 256, 256>>>(W);
    k_deg_count<<<(N_EDGES + 255) / 256, 256>>>(ei);
    k_scan1    <<<SCAN_NB, 256>>>();
    k_scan2    <<<1, 128>>>();
    k_scan3    <<<SCAN_NB, 256>>>();
    k_csr      <<<(N_EDGES + 255) / 256, 256>>>(ei);
    k_linear   <<<(N_NODES + NODES_PER_BLK - 1) / NODES_PER_BLK, 256>>>(x);
    k_aggregate<<<(N_NODES * 32) / 256, 256>>>(b, out);
}